// round 5
// baseline (speedup 1.0000x reference)
#include <cuda_runtime.h>
#include <math.h>

#define Hs    64
#define SEQ   2048
#define Bt    256
#define IN    32
#define GATES 256   // 4*H

typedef unsigned long long u64;

__device__ float g_xproj[(size_t)SEQ * Bt * GATES];   // [t][row][g], bias0 folded

__device__ __forceinline__ u64 fma2(u64 a, u64 b, u64 c) {
    u64 d;
    asm("fma.rn.f32x2 %0, %1, %2, %3;" : "=l"(d) : "l"(a), "l"(b), "l"(c));
    return d;
}
__device__ __forceinline__ u64 pk(float a, float b) {
    u64 r;
    asm("mov.b64 %0, {%1, %2};" : "=l"(r) : "f"(a), "f"(b));
    return r;
}
__device__ __forceinline__ float hsum(u64 v) {
    float a, b;
    asm("mov.b64 {%0, %1}, %2;" : "=f"(a), "=f"(b) : "l"(v));
    return a + b;
}
__device__ __forceinline__ float ex2a(float x) {
    float y; asm("ex2.approx.f32 %0, %1;" : "=f"(y) : "f"(x)); return y;
}
__device__ __forceinline__ float rcpa(float x) {
    float y; asm("rcp.approx.f32 %0, %1;" : "=f"(y) : "f"(x)); return y;
}
__device__ __forceinline__ float sigf(float x) {
    return rcpa(1.0f + ex2a(-1.4426950408889634f * x));
}
__device__ __forceinline__ float tanhfa(float x) {
    return fmaf(2.0f, sigf(2.0f * x), -1.0f);
}

// ============================================================================
// Prepass: xproj[t][row][g] = Wih0[g]·x[row][t] + bih0[g] + bhh0[g]
// ============================================================================
__global__ void __launch_bounds__(256)
xproj_kernel(const float* __restrict__ x,
             const float* __restrict__ Wih0,
             const float* __restrict__ bih0,
             const float* __restrict__ bhh0)
{
    __shared__ float sx[64 * IN];
    const int g   = threadIdx.x;
    const int row = blockIdx.y;
    const int t0  = blockIdx.x * 64;

    const float* xs = x + ((size_t)row * SEQ + t0) * IN;
    for (int i = g; i < 64 * IN / 4; i += 256)
        ((float4*)sx)[i] = ((const float4*)xs)[i];

    u64 w[IN / 2];
    const u64* wp = (const u64*)(Wih0 + g * IN);
#pragma unroll
    for (int k = 0; k < IN / 2; k++) w[k] = wp[k];
    const u64 bp = pk(bih0[g] + bhh0[g], 0.0f);
    __syncthreads();

    for (int tt = 0; tt < 64; tt++) {
        const ulonglong2* xv = (const ulonglong2*)(sx + tt * IN);
        u64 a = bp;
#pragma unroll
        for (int k = 0; k < IN / 4; k++) {
            ulonglong2 v = xv[k];
            a = fma2(w[2 * k],     v.x, a);
            a = fma2(w[2 * k + 1], v.y, a);
        }
        g_xproj[((size_t)(t0 + tt) * Bt + row) * GATES + g] = hsum(a);
    }
}

// ============================================================================
// Main: 128 CTAs x 512 threads. tid = j*8 + gate*2 + half.
// Thread holds half-rows of Whh0, Wih1, Whh1 (96 regs). Shuffle combine,
// role-packed cell updates, double-buffered h, ONE barrier per step.
// ============================================================================
__global__ void __launch_bounds__(512, 1)
lstm2_shfl(const float* __restrict__ h0g,
           const float* __restrict__ c0g,
           const float* __restrict__ Whh0,
           const float* __restrict__ Wih1,
           const float* __restrict__ Whh1,
           const float* __restrict__ bih1,
           const float* __restrict__ bhh1,
           const float* __restrict__ Wh,
           const float* __restrict__ bhp,
           float* __restrict__ out)
{
    __shared__ float sH0[2][2][Hs];   // [buf][row][j]
    __shared__ float sH1[2][2][Hs];
    __shared__ float sPr[2][16][2];   // [parity][warp][row]

    const int tid  = threadIdx.x;
    const int j    = tid >> 3;          // 0..63
    const int gate = (tid >> 1) & 3;    // 0..3
    const int half = tid & 1;           // 0..1
    const int g    = gate * 64 + j;
    const int lane = tid & 31;
    const int role = tid & 7;           // 0..7; 0..3 are update roles
    const int ob   = lane & 24;         // octet base lane
    const int wid  = tid >> 5;
    const int r0   = blockIdx.x * 2;

    // register weights: half-rows (32 floats = 16 u64 each)
    u64 wh0[16], wx1[16], wh1[16];
    {
        const u64* p0 = (const u64*)(Whh0 + g * Hs + half * 32);
        const u64* p1 = (const u64*)(Wih1 + g * Hs + half * 32);
        const u64* p2 = (const u64*)(Whh1 + g * Hs + half * 32);
#pragma unroll
        for (int k = 0; k < 16; k++) { wh0[k] = p0[k]; wx1[k] = p1[k]; wh1[k] = p2[k]; }
    }
    const float b1  = bih1[g] + bhh1[g];
    const float whj = Wh[j];
    const float bh0 = bhp[0];

    // state init: role lanes own c for (layer=role>>1, row=role&1, j)
    float c = 0.0f;
    if (role < 4) {
        int layer = role >> 1, row = role & 1;
        c = c0g[(size_t)layer * Bt * Hs + (size_t)(r0 + row) * Hs + j];
        if (layer == 0) {
            float h = h0g[(size_t)(r0 + row) * Hs + j];
            sH0[0][row][j] = h; sH0[1][row][j] = h;
        } else {
            float h = h0g[(size_t)Bt * Hs + (size_t)(r0 + row) * Hs + j];
            sH1[0][row][j] = h; sH1[1][row][j] = h;
        }
    }
    float xp = g_xproj[((size_t)0 * Bt + r0 + half) * GATES + g];
    __syncthreads();

    for (int u = 0; u <= SEQ; u++) {
        // prefetch xproj(u+1) into register (full step of latency cover)
        float xpn = 0.0f;
        if (u + 1 < SEQ)
            xpn = g_xproj[((size_t)(u + 1) * Bt + r0 + half) * GATES + g];

        const ulonglong2* H0 = (const ulonglong2*)&sH0[u & 1][0][0];
        const ulonglong2* H1 = (const ulonglong2*)&sH1[u & 1][0][0];

        u64 a0, a1, q0, q1;
        if (half == 0) { a0 = pk(xp, 0.f); a1 = 0ULL; q0 = pk(b1, 0.f); q1 = 0ULL; }
        else           { a0 = 0ULL; a1 = pk(xp, 0.f); q0 = 0ULL; q1 = pk(b1, 0.f); }

#pragma unroll
        for (int k = 0; k < 8; k++) {          // h0 operand feeds Whh0 AND Wih1
            ulonglong2 v0 = H0[half * 8 + k];
            ulonglong2 v1 = H0[16 + half * 8 + k];
            a0 = fma2(wh0[2*k],   v0.x, a0);
            a0 = fma2(wh0[2*k+1], v0.y, a0);
            a1 = fma2(wh0[2*k],   v1.x, a1);
            a1 = fma2(wh0[2*k+1], v1.y, a1);
            q0 = fma2(wx1[2*k],   v0.x, q0);
            q0 = fma2(wx1[2*k+1], v0.y, q0);
            q1 = fma2(wx1[2*k],   v1.x, q1);
            q1 = fma2(wx1[2*k+1], v1.y, q1);
        }
#pragma unroll
        for (int k = 0; k < 8; k++) {          // Whh1 over h1
            ulonglong2 v0 = H1[half * 8 + k];
            ulonglong2 v1 = H1[16 + half * 8 + k];
            q0 = fma2(wh1[2*k],   v0.x, q0);
            q0 = fma2(wh1[2*k+1], v0.y, q0);
            q1 = fma2(wh1[2*k],   v1.x, q1);
            q1 = fma2(wh1[2*k+1], v1.y, q1);
        }

        // collapse accumulators, sum across K-halves
        float A0 = hsum(a0), A1 = hsum(a1), Q0 = hsum(q0), Q1 = hsum(q1);
        A0 += __shfl_xor_sync(0xffffffffu, A0, 1);
        A1 += __shfl_xor_sync(0xffffffffu, A1, 1);
        Q0 += __shfl_xor_sync(0xffffffffu, Q0, 1);
        Q1 += __shfl_xor_sync(0xffffffffu, Q1, 1);

        // gather i,f,g,o for this octet's role from the 4 gate lanes
        float I = 0.f, F = 0.f, G = 0.f, O = 0.f;
        {
            float vi = __shfl_sync(0xffffffffu, A0, ob + 0);
            float vf = __shfl_sync(0xffffffffu, A0, ob + 2);
            float vg = __shfl_sync(0xffffffffu, A0, ob + 4);
            float vo = __shfl_sync(0xffffffffu, A0, ob + 6);
            if (role == 0) { I = vi; F = vf; G = vg; O = vo; }
        }
        {
            float vi = __shfl_sync(0xffffffffu, A1, ob + 0);
            float vf = __shfl_sync(0xffffffffu, A1, ob + 2);
            float vg = __shfl_sync(0xffffffffu, A1, ob + 4);
            float vo = __shfl_sync(0xffffffffu, A1, ob + 6);
            if (role == 1) { I = vi; F = vf; G = vg; O = vo; }
        }
        {
            float vi = __shfl_sync(0xffffffffu, Q0, ob + 0);
            float vf = __shfl_sync(0xffffffffu, Q0, ob + 2);
            float vg = __shfl_sync(0xffffffffu, Q0, ob + 4);
            float vo = __shfl_sync(0xffffffffu, Q0, ob + 6);
            if (role == 2) { I = vi; F = vf; G = vg; O = vo; }
        }
        {
            float vi = __shfl_sync(0xffffffffu, Q1, ob + 0);
            float vf = __shfl_sync(0xffffffffu, Q1, ob + 2);
            float vg = __shfl_sync(0xffffffffu, Q1, ob + 4);
            float vo = __shfl_sync(0xffffffffu, Q1, ob + 6);
            if (role == 3) { I = vi; F = vf; G = vg; O = vo; }
        }

        // cell update (packed: one warp-instr set serves all 4 roles)
        float si = sigf(I), sf = sigf(F), sg = tanhfa(G), so = sigf(O);
        float cn = sf * c + si * sg;
        float hn = so * tanhfa(cn);
        bool updL0 = (role < 2) && (u < SEQ);
        bool updL1 = (role == 2 || role == 3) && (u >= 1);
        if (updL0) {
            c = cn;
            sH0[(u + 1) & 1][role & 1][j] = hn;
        }
        if (updL1) {
            c = cn;
            sH1[(u + 1) & 1][role & 1][j] = hn;
        }

        // head partials: layer-1 roles contribute hn*Wh[j]; reduce 4 octets
        float p = updL1 ? hn * whj : 0.0f;
        p += __shfl_xor_sync(0xffffffffu, p, 8);
        p += __shfl_xor_sync(0xffffffffu, p, 16);
        if (u >= 1 && (lane == 2 || lane == 3))
            sPr[u & 1][wid][lane - 2] = p;

        // head output for time u-2 (partials from iteration u-1)
        if (u >= 2 && (tid == 508 || tid == 509)) {
            int row = tid - 508;
            float v = bh0;
#pragma unroll
            for (int w = 0; w < 16; w++) v += sPr[(u - 1) & 1][w][row];
            out[(size_t)(r0 + row) * SEQ + (u - 2)] = sigf(v);
        }

        xp = xpn;
        __syncthreads();
    }

    // final head output for t=SEQ-1 (partials written at iter u=SEQ)
    if (tid == 508 || tid == 509) {
        int row = tid - 508;
        float v = bh0;
#pragma unroll
        for (int w = 0; w < 16; w++) v += sPr[SEQ & 1][w][row];
        out[(size_t)(r0 + row) * SEQ + (SEQ - 1)] = sigf(v);
    }

    // final h, c
    const size_t hb = (size_t)Bt * SEQ;
    const size_t cb = hb + 2 * (size_t)Bt * Hs;
    if (role < 4) {
        int layer = role >> 1, row = role & 1;
        out[cb + (size_t)layer * Bt * Hs + (size_t)(r0 + row) * Hs + j] = c;
        if (layer == 0)
            out[hb + (size_t)(r0 + row) * Hs + j] = sH0[SEQ & 1][row][j];
        else
            out[hb + (size_t)Bt * Hs + (size_t)(r0 + row) * Hs + j] = sH1[(SEQ + 1) & 1][row][j];
    }
}

extern "C" void kernel_launch(void* const* d_in, const int* in_sizes, int n_in,
                              void* d_out, int out_size)
{
    const float* x    = (const float*)d_in[0];
    const float* h0   = (const float*)d_in[1];
    const float* c0   = (const float*)d_in[2];
    const float* Wih0 = (const float*)d_in[3];
    const float* Whh0 = (const float*)d_in[4];
    const float* bih0 = (const float*)d_in[5];
    const float* bhh0 = (const float*)d_in[6];
    const float* Wih1 = (const float*)d_in[7];
    const float* Whh1 = (const float*)d_in[8];
    const float* bih1 = (const float*)d_in[9];
    const float* bhh1 = (const float*)d_in[10];
    const float* Wh   = (const float*)d_in[11];
    const float* bh   = (const float*)d_in[12];
    float* out = (float*)d_out;

    dim3 pre_grid(SEQ / 64, Bt);
    xproj_kernel<<<pre_grid, 256>>>(x, Wih0, bih0, bhh0);
    lstm2_shfl<<<Bt / 2, 512>>>(h0, c0, Whh0, Wih1, Whh1,
                                bih1, bhh1, Wh, bh, out);
}